// round 17
// baseline (speedup 1.0000x reference)
#include <cuda_runtime.h>
#include <cstdint>

#define DIM     4096
#define NEXP    64
#define BM      128
#define BK      32
#define NITER   (DIM / BK)       // 128
#define THREADS 256
#define APAD    36               // A row stride (floats): conflict-free scalar LDS
#define AFLOATS (BM * APAD)      // 4608
#define BPAD4   66               // B (tig,row) block stride in float4 units
#define BF4     (16 * BPAD4)     // 1056 float4 per stage
#define STAGEF  (AFLOATS + BF4 * 4)   // 8832 floats = 35328 B
#define NSTAGE  4
#define LPAD    68
#define DYN_SMEM (NSTAGE * STAGEF * 4)   // 141312 B

// Pre-split W: [512 blk][64 row][4 tig] float4 = {hi_k, hi_k+4, lo_k, lo_k+4}
__device__ float4 g_Wp[512 * 64 * 4];    // 8 MB

// ---------------- helpers ----------------
__device__ __forceinline__ uint32_t sptr(const void* p) {
    return (uint32_t)__cvta_generic_to_shared(p);
}
__device__ __forceinline__ void cpa16(uint32_t d, const void* s) {
    asm volatile("cp.async.cg.shared.global [%0], [%1], 16;" :: "r"(d), "l"(s));
}
__device__ __forceinline__ void cpc()  { asm volatile("cp.async.commit_group;" ::: "memory"); }
__device__ __forceinline__ void cpw2() { asm volatile("cp.async.wait_group 2;" ::: "memory"); }

__device__ __forceinline__ uint32_t tfhi(float v) {
    uint32_t r; asm("cvt.rna.tf32.f32 %0, %1;" : "=r"(r) : "f"(v)); return r;
}
__device__ __forceinline__ void mma8(float* d, const uint32_t* a, uint32_t b0, uint32_t b1) {
    asm volatile(
        "mma.sync.aligned.m16n8k8.row.col.f32.tf32.tf32.f32 "
        "{%0,%1,%2,%3}, {%4,%5,%6,%7}, {%8,%9}, {%0,%1,%2,%3};"
        : "+f"(d[0]), "+f"(d[1]), "+f"(d[2]), "+f"(d[3])
        : "r"(a[0]), "r"(a[1]), "r"(a[2]), "r"(a[3]), "r"(b0), "r"(b1));
}

// ---------------- prep: split W into packed hi/lo float4 plane ----------------
__global__ void prep_w(const float* __restrict__ W) {
    const int i   = blockIdx.x * blockDim.x + threadIdx.x;   // 0..131071
    const int blk = i >> 8;
    const int r   = (i >> 2) & 63;
    const int tig = i & 3;
    const int k   = blk * 8 + tig;
    const float v0 = W[(size_t)r * DIM + k];
    const float v1 = W[(size_t)r * DIM + k + 4];
    const uint32_t h0 = tfhi(v0), h1 = tfhi(v1);
    const uint32_t l0 = tfhi(v0 - __uint_as_float(h0));
    const uint32_t l1 = tfhi(v1 - __uint_as_float(h1));
    g_Wp[i] = make_float4(__uint_as_float(h0), __uint_as_float(h1),
                          __uint_as_float(l0), __uint_as_float(l1));
}

// ---------------- stage loader ----------------
__device__ __forceinline__ void load_stage(float* sm, int buf, const float* x,
                                           int m0, int k0, int it, int tid) {
    float* As = sm + buf * STAGEF;
#pragma unroll
    for (int p = 0; p < 4; p++) {                 // A: 128 rows x 128B
        int idx = tid + p * THREADS;
        int row = idx >> 3, c = idx & 7;
        cpa16(sptr(As + row * APAD + c * 4),
              x + (size_t)(m0 + row) * DIM + k0 + c * 4);
    }
    float4* Bs = (float4*)(As + AFLOATS);
    const float4* src = g_Wp + (size_t)it * 1024;  // contiguous stage block
#pragma unroll
    for (int p = 0; p < 4; p++) {                 // B: 1024 float4
        int i = tid + p * THREADS;
        int blkL = i >> 8, r = (i >> 2) & 63, tig = i & 3;
        cpa16(sptr(Bs + (blkL * 4 + tig) * BPAD4 + r), src + i);
    }
}

// ---------------- fused gate kernel ----------------
__global__ void __launch_bounds__(THREADS, 1)
gate_mma(const float* __restrict__ x, float* __restrict__ out, int N, int with_idx)
{
    extern __shared__ __align__(16) float sm[];
    const int tid  = threadIdx.x;
    const int wid  = tid >> 5;
    const int lane = tid & 31;
    const int gid  = lane >> 2;          // 0..7
    const int tig  = lane & 3;           // 0..3
    const int wm   = (wid & 3) * 32;     // 4 M-warps
    const int wn   = (wid >> 2) * 32;    // 2 N-warps
    const int m0   = blockIdx.x * BM;

    float acc[2][4][4];
#pragma unroll
    for (int mt = 0; mt < 2; mt++)
#pragma unroll
        for (int nt = 0; nt < 4; nt++)
#pragma unroll
            for (int q = 0; q < 4; q++) acc[mt][nt][q] = 0.0f;

#pragma unroll
    for (int s = 0; s < NSTAGE - 1; s++) {
        load_stage(sm, s, x, m0, s * BK, s, tid);
        cpc();
    }

    for (int it = 0; it < NITER; it++) {
        const int buf = it & (NSTAGE - 1);
        cpw2();
        __syncthreads();

        if (it + NSTAGE - 1 < NITER)
            load_stage(sm, (it + NSTAGE - 1) & (NSTAGE - 1), x, m0,
                       (it + NSTAGE - 1) * BK, it + NSTAGE - 1, tid);
        cpc();

        const float* As = sm + buf * STAGEF;
        const float4* Bs = (const float4*)(As + AFLOATS);
        const float* pa = As + (wm + gid) * APAD;
        const int pbrow = wn + gid;

#pragma unroll
        for (int ks = 0; ks < 4; ks++) {          // 4 x k8 per BK=32
            const int k = ks * 8 + tig;
            uint32_t ah[2][4], al[2][4];
#pragma unroll
            for (int mt = 0; mt < 2; mt++) {
                const float* q = pa + mt * 16 * APAD;
                const float v0 = q[k];
                const float v1 = q[8 * APAD + k];
                const float v2 = q[k + 4];
                const float v3 = q[8 * APAD + k + 4];
                ah[mt][0] = tfhi(v0); al[mt][0] = __float_as_uint(v0 - __uint_as_float(ah[mt][0]));
                ah[mt][1] = tfhi(v1); al[mt][1] = __float_as_uint(v1 - __uint_as_float(ah[mt][1]));
                ah[mt][2] = tfhi(v2); al[mt][2] = __float_as_uint(v2 - __uint_as_float(ah[mt][2]));
                ah[mt][3] = tfhi(v3); al[mt][3] = __float_as_uint(v3 - __uint_as_float(ah[mt][3]));
            }
            float4 b[4];
#pragma unroll
            for (int nt = 0; nt < 4; nt++)
                b[nt] = Bs[(ks * 4 + tig) * BPAD4 + pbrow + nt * 8];

            // 3 terms, each swept across all 8 acc tiles (same-acc distance = 8)
#pragma unroll
            for (int mt = 0; mt < 2; mt++)
#pragma unroll
                for (int nt = 0; nt < 4; nt++)
                    mma8(acc[mt][nt], ah[mt], __float_as_uint(b[nt].x), __float_as_uint(b[nt].y));
#pragma unroll
            for (int mt = 0; mt < 2; mt++)
#pragma unroll
                for (int nt = 0; nt < 4; nt++)
                    mma8(acc[mt][nt], ah[mt], __float_as_uint(b[nt].z), __float_as_uint(b[nt].w));
#pragma unroll
            for (int mt = 0; mt < 2; mt++)
#pragma unroll
                for (int nt = 0; nt < 4; nt++)
                    mma8(acc[mt][nt], al[mt], __float_as_uint(b[nt].x), __float_as_uint(b[nt].y));
        }
    }

    // ---------------- epilogue: logits -> top-2 -> softmax -> scatter ----------------
    __syncthreads();
    float* ls = sm;                       // overlay: [128][LPAD]

#pragma unroll
    for (int mt = 0; mt < 2; mt++)
#pragma unroll
        for (int nt = 0; nt < 4; nt++) {
            const int r = wm + mt * 16 + gid;
            const int c = wn + nt * 8 + tig * 2;
            *(float2*)(ls + r * LPAD + c)       = make_float2(acc[mt][nt][0], acc[mt][nt][1]);
            *(float2*)(ls + (r + 8) * LPAD + c) = make_float2(acc[mt][nt][2], acc[mt][nt][3]);
        }
    __syncthreads();

    if (tid < BM) {
        float* row = ls + tid * LPAD;
        float v1 = -3.4e38f, v2 = -3.4e38f;
        int   i1 = 0, i2 = 0;
#pragma unroll
        for (int j = 0; j < NEXP; j++) {          // ties -> lower index (JAX top_k)
            float v = row[j];
            if (v > v1)      { v2 = v1; i2 = i1; v1 = v; i1 = j; }
            else if (v > v2) { v2 = v;  i2 = j; }
        }
        const float e2 = expf(v2 - v1);
        const float ss = 1.0f / (1.0f + e2);
        const float w1 = ss, w2 = e2 * ss;
#pragma unroll
        for (int j = 0; j < NEXP; j++) row[j] = 0.0f;
        row[i1] = w1;
        row[i2] = w2;
        if (with_idx) {
            *(float2*)(out + (size_t)N * NEXP + (size_t)(m0 + tid) * 2) =
                make_float2((float)i1, (float)i2);
        }
    }
    __syncthreads();

    for (int q = tid; q < BM * NEXP / 4; q += THREADS) {
        const int i = q * 4;
        const int r = i >> 6, c = i & 63;
        float4 v = *(const float4*)(ls + r * LPAD + c);
        *(float4*)(out + (size_t)m0 * NEXP + i) = v;
    }
}

// ---------------- launch ----------------
extern "C" void kernel_launch(void* const* d_in, const int* in_sizes, int n_in,
                              void* d_out, int out_size) {
    const float* x  = (const float*)d_in[0];   // [N, 4096]
    const float* Wm = (const float*)d_in[1];   // [64, 4096]
    const int N = in_sizes[0] / DIM;           // 16384

    prep_w<<<512, 256>>>(Wm);

    cudaFuncSetAttribute(gate_mma, cudaFuncAttributeMaxDynamicSharedMemorySize,
                         DYN_SMEM);
    const int with_idx = (out_size >= N * NEXP + N * 2) ? 1 : 0;
    gate_mma<<<N / BM, THREADS, DYN_SMEM>>>(x, (float*)d_out, N, with_idx);
}